// round 6
// baseline (speedup 1.0000x reference)
#include <cuda_runtime.h>
#include <cstdint>

#define NN 100000
#define NE 600000
#define SCAN_B 1024
#define NBLK ((NN + SCAN_B - 1) / SCAN_B)   // 98

// Scratch (device globals: no allocation allowed anywhere).
__device__ __align__(16) int   g_deg[NN];
__device__ __align__(16) int   g_cnt[NN];
__device__ __align__(16) int   g_rowstart[NN + 1];
__device__ __align__(16) int   g_blocksum[NBLK];
__device__ __align__(16) int   g_csr[NE];
__device__ __align__(16) float g_dinv[NN];
__device__ __align__(16) float g_g1[NN * 128];  // dinv * (x @ W1)
__device__ __align__(16) float g_h1[NN * 128];  // relu(dinv*agg + b1)
__device__ __align__(16) float g_g2[NN * 64];   // dinv * (h1 @ W2)
__device__ int g_is64;                          // edge index storage layout flag

// Edge accessors: branch on detected layout (int32 words vs int64).
__device__ __forceinline__ int edge_src(const int* ei, int e) {
    return g_is64 ? (int)((const long long*)ei)[e] : ei[e];
}
__device__ __forceinline__ int edge_dst(const int* ei, int e) {
    return g_is64 ? (int)((const long long*)ei)[NE + e] : ei[NE + e];
}

// ---------------------------------------------------------------- detect
// If edges are int64 (values < 2^31), every odd 32-bit word is zero.
__global__ void k_detect(const int* __restrict__ ei) {
    __shared__ int flag;
    if (threadIdx.x == 0) flag = 0;
    __syncthreads();
    int any = 0;
    for (int i = threadIdx.x; i < 4096; i += 256)
        if (ei[2 * i + 1] != 0) any = 1;
    if (any) flag = 1;
    __syncthreads();
    if (threadIdx.x == 0) g_is64 = flag ? 0 : 1;
}

// ---------------------------------------------------------------- init
__global__ void k_zero() {
    int i = blockIdx.x * blockDim.x + threadIdx.x;
    if (i < NN) { g_deg[i] = 0; g_cnt[i] = 0; }
}

__global__ void k_count(const int* __restrict__ ei) {
    int e = blockIdx.x * blockDim.x + threadIdx.x;
    if (e < NE) {
        int d = edge_dst(ei, e);
        if (d >= 0 && d < NN) atomicAdd(&g_deg[d], 1);
    }
}

__global__ void k_dinv() {
    int i = blockIdx.x * blockDim.x + threadIdx.x;
    if (i < NN) g_dinv[i] = rsqrtf((float)(g_deg[i] + 1));
}

// ---------------------------------------------------------------- scan
__global__ void __launch_bounds__(SCAN_B) k_scan_local() {
    __shared__ int s[SCAN_B];
    int tid = threadIdx.x;
    int gid = blockIdx.x * SCAN_B + tid;
    int v = (gid < NN) ? g_deg[gid] : 0;
    s[tid] = v;
    __syncthreads();
#pragma unroll
    for (int off = 1; off < SCAN_B; off <<= 1) {
        int t = (tid >= off) ? s[tid - off] : 0;
        __syncthreads();
        s[tid] += t;
        __syncthreads();
    }
    if (gid < NN) g_rowstart[gid] = s[tid] - v;           // exclusive
    if (tid == SCAN_B - 1) g_blocksum[blockIdx.x] = s[tid];
}

__global__ void k_scan_blocks() {
    __shared__ int s[NBLK];
    int tid = threadIdx.x;
    if (tid < NBLK) s[tid] = g_blocksum[tid];
    __syncthreads();
    if (tid == 0) {
        int run = 0;
        for (int i = 0; i < NBLK; i++) { int t = s[i]; s[i] = run; run += t; }
        g_rowstart[NN] = run;
    }
    __syncthreads();
    if (tid < NBLK) g_blocksum[tid] = s[tid];
}

__global__ void __launch_bounds__(SCAN_B) k_scan_add() {
    int gid = blockIdx.x * SCAN_B + threadIdx.x;
    if (gid < NN) g_rowstart[gid] += g_blocksum[blockIdx.x];
}

// ---------------------------------------------------------------- CSR fill
__global__ void k_fill(const int* __restrict__ ei) {
    int e = blockIdx.x * blockDim.x + threadIdx.x;
    if (e >= NE) return;
    int s = edge_src(ei, e);
    int d = edge_dst(ei, e);
    if (s < 0 || s >= NN || d < 0 || d >= NN) return;
    int pos = g_rowstart[d] + atomicAdd(&g_cnt[d], 1);
    g_csr[pos] = s;
}

// ---------------------------------------------------------------- GEMM1
// g1[i][j] = dinv[i] * sum_k x[i][k] * W1[k][j]
__global__ void __launch_bounds__(256) k_gemm1(const float* __restrict__ x,
                                               const float* __restrict__ W) {
    extern __shared__ float sm[];
    float* sW = sm;              // 128*128
    float* sX = sm + 128 * 128;  // 64*128
    int tid = threadIdx.x;
    int row0 = blockIdx.x * 64;

    for (int i = tid; i < 128 * 128 / 4; i += 256)
        ((float4*)sW)[i] = ((const float4*)W)[i];
    for (int i = tid; i < 64 * 128 / 4; i += 256) {
        int r = i >> 5;
        int gr = row0 + r;
        ((float4*)sX)[i] = (gr < NN) ? ((const float4*)x)[gr * 32 + (i & 31)]
                                     : make_float4(0.f, 0.f, 0.f, 0.f);
    }
    __syncthreads();

    int c = tid & 31;
    int r = tid >> 5;
    float4 acc[8];
#pragma unroll
    for (int i = 0; i < 8; i++) acc[i] = make_float4(0.f, 0.f, 0.f, 0.f);

#pragma unroll 4
    for (int k = 0; k < 128; k++) {
        float4 w = ((const float4*)sW)[k * 32 + c];
#pragma unroll
        for (int i = 0; i < 8; i++) {
            float xv = sX[(r + 8 * i) * 128 + k];
            acc[i].x += xv * w.x;
            acc[i].y += xv * w.y;
            acc[i].z += xv * w.z;
            acc[i].w += xv * w.w;
        }
    }

#pragma unroll
    for (int i = 0; i < 8; i++) {
        int gr = row0 + r + 8 * i;
        if (gr < NN) {
            float s = g_dinv[gr];
            ((float4*)g_g1)[gr * 32 + c] =
                make_float4(s * acc[i].x, s * acc[i].y, s * acc[i].z, s * acc[i].w);
        }
    }
}

// ---------------------------------------------------------------- aggregate1
// One warp per node: h1[n] = relu(dinv[n]*(g1[n] + sum_{s->n} g1[s]) + b1)
__global__ void __launch_bounds__(256) k_agg1(const float* __restrict__ b1) {
    int node = (blockIdx.x * 256 + threadIdx.x) >> 5;
    int lane = threadIdx.x & 31;
    if (node >= NN) return;
    int beg = g_rowstart[node];
    int end = g_rowstart[node + 1];
    float4 acc = ((const float4*)g_g1)[node * 32 + lane];   // self loop
    for (int i = beg; i < end; i++) {
        int s = g_csr[i];
        float4 v = ((const float4*)g_g1)[s * 32 + lane];
        acc.x += v.x; acc.y += v.y; acc.z += v.z; acc.w += v.w;
    }
    float dn = g_dinv[node];
    float4 o;
    o.x = fmaxf(fmaf(dn, acc.x, __ldg(&b1[lane * 4 + 0])), 0.f);
    o.y = fmaxf(fmaf(dn, acc.y, __ldg(&b1[lane * 4 + 1])), 0.f);
    o.z = fmaxf(fmaf(dn, acc.z, __ldg(&b1[lane * 4 + 2])), 0.f);
    o.w = fmaxf(fmaf(dn, acc.w, __ldg(&b1[lane * 4 + 3])), 0.f);
    ((float4*)g_h1)[node * 32 + lane] = o;
}

// ---------------------------------------------------------------- GEMM2
// g2[i][j] = dinv[i] * sum_k h1[i][k] * W2[k][j]
__global__ void __launch_bounds__(256) k_gemm2(const float* __restrict__ W2) {
    extern __shared__ float sm[];
    float* sW = sm;             // 128*64
    float* sX = sm + 128 * 64;  // 64*128
    int tid = threadIdx.x;
    int row0 = blockIdx.x * 64;

    for (int i = tid; i < 128 * 64 / 4; i += 256)
        ((float4*)sW)[i] = ((const float4*)W2)[i];
    for (int i = tid; i < 64 * 128 / 4; i += 256) {
        int r = i >> 5;
        int gr = row0 + r;
        ((float4*)sX)[i] = (gr < NN) ? ((const float4*)g_h1)[gr * 32 + (i & 31)]
                                     : make_float4(0.f, 0.f, 0.f, 0.f);
    }
    __syncthreads();

    int c = tid & 15;
    int r = tid >> 4;
    float4 acc[4];
#pragma unroll
    for (int i = 0; i < 4; i++) acc[i] = make_float4(0.f, 0.f, 0.f, 0.f);

#pragma unroll 4
    for (int k = 0; k < 128; k++) {
        float4 w = ((const float4*)sW)[k * 16 + c];
#pragma unroll
        for (int i = 0; i < 4; i++) {
            float xv = sX[(r + 16 * i) * 128 + k];
            acc[i].x += xv * w.x;
            acc[i].y += xv * w.y;
            acc[i].z += xv * w.z;
            acc[i].w += xv * w.w;
        }
    }

#pragma unroll
    for (int i = 0; i < 4; i++) {
        int gr = row0 + r + 16 * i;
        if (gr < NN) {
            float s = g_dinv[gr];
            ((float4*)g_g2)[gr * 16 + c] =
                make_float4(s * acc[i].x, s * acc[i].y, s * acc[i].z, s * acc[i].w);
        }
    }
}

// ---------------------------------------------------------------- aggregate2
// 16 lanes per node (64 floats): out[n] = dinv[n]*(g2[n] + sum g2[s]) + b2
__global__ void __launch_bounds__(256) k_agg2(const float* __restrict__ b2,
                                              float* __restrict__ out) {
    int t = blockIdx.x * 256 + threadIdx.x;
    int node = t >> 4;
    int l = t & 15;
    if (node >= NN) return;
    int beg = g_rowstart[node];
    int end = g_rowstart[node + 1];
    float4 acc = ((const float4*)g_g2)[node * 16 + l];      // self loop
    for (int i = beg; i < end; i++) {
        int s = g_csr[i];
        float4 v = ((const float4*)g_g2)[s * 16 + l];
        acc.x += v.x; acc.y += v.y; acc.z += v.z; acc.w += v.w;
    }
    float dn = g_dinv[node];
    float4 o;
    o.x = fmaf(dn, acc.x, __ldg(&b2[l * 4 + 0]));
    o.y = fmaf(dn, acc.y, __ldg(&b2[l * 4 + 1]));
    o.z = fmaf(dn, acc.z, __ldg(&b2[l * 4 + 2]));
    o.w = fmaf(dn, acc.w, __ldg(&b2[l * 4 + 3]));
    ((float4*)out)[node * 16 + l] = o;
}

// ----------------------------------------------------------------
extern "C" void kernel_launch(void* const* d_in, const int* in_sizes, int n_in,
                              void* d_out, int out_size) {
    const float* x  = (const float*)d_in[0];
    const int*   ei = (const int*)d_in[1];
    const float* W1 = (const float*)d_in[2];
    const float* b1 = (const float*)d_in[3];
    const float* W2 = (const float*)d_in[4];
    const float* b2 = (const float*)d_in[5];
    float* out = (float*)d_out;

    const int smem1 = (128 * 128 + 64 * 128) * 4;  // 96 KB
    const int smem2 = (128 * 64 + 64 * 128) * 4;   // 64 KB
    cudaFuncSetAttribute(k_gemm1, cudaFuncAttributeMaxDynamicSharedMemorySize, smem1);
    cudaFuncSetAttribute(k_gemm2, cudaFuncAttributeMaxDynamicSharedMemorySize, smem2);

    k_detect<<<1, 256>>>(ei);
    k_zero <<<(NN + 255) / 256, 256>>>();
    k_count<<<(NE + 255) / 256, 256>>>(ei);
    k_scan_local <<<NBLK, SCAN_B>>>();
    k_scan_blocks<<<1, 128>>>();
    k_scan_add   <<<NBLK, SCAN_B>>>();
    k_dinv <<<(NN + 255) / 256, 256>>>();
    k_fill <<<(NE + 255) / 256, 256>>>(ei);

    k_gemm1<<<(NN + 63) / 64, 256, smem1>>>(x, W1);
    k_agg1 <<<(NN * 32 + 255) / 256, 256>>>(b1);

    k_gemm2<<<(NN + 63) / 64, 256, smem2>>>(W2);
    k_agg2 <<<(NN * 16 + 255) / 256, 256>>>(b2, out);
}